// round 15
// baseline (speedup 1.0000x reference)
#include <cuda_runtime.h>

#define H  2048
#define SW 256
#define SD 200
#define O  128
#define IH (H + SW)   // 2304

#define NB_PROL 259          // K1: 3 ctrl + 256 s_in dots
#define NB_GRUT (3 * H)      // K1: 6144 gate-row tasks
#define NB_GRU2 256          // K2a: 8 rows per block (warp per row)
#define NB_STK  50           // K2a: stack blocks (4 depth rows each)
#define NB_DEC  128          // K2b: decoder blocks

// ---- scratch (device globals) ----
__device__ float g_logits[3];
__device__ float g_sin[SW];
__device__ float g_pr[H];    // Wih_r[:H]·x + Whh_r·h
__device__ float g_pz[H];
__device__ float g_pgin[H];  // Wih_n[:H]·x
__device__ float g_pghn[H];  // Whh_n·h
__device__ float g_hnew[H];

struct F8 { float4 lo, hi; };

__device__ __forceinline__ float dot4(float4 a, float4 b) {
    return a.x*b.x + a.y*b.y + a.z*b.z + a.w*b.w;
}

// 256-bit read-only weight load (keeps LDG count low; evict hint kept —
// measured neutral-to-positive).
__device__ __forceinline__ F8 ldg_w8(const float* p) {
    unsigned r0, r1, r2, r3, r4, r5, r6, r7;
    asm("ld.global.nc.L2::evict_last.v8.b32 {%0,%1,%2,%3,%4,%5,%6,%7}, [%8];"
        : "=r"(r0), "=r"(r1), "=r"(r2), "=r"(r3),
          "=r"(r4), "=r"(r5), "=r"(r6), "=r"(r7)
        : "l"(p));
    F8 v;
    v.lo.x = __uint_as_float(r0); v.lo.y = __uint_as_float(r1);
    v.lo.z = __uint_as_float(r2); v.lo.w = __uint_as_float(r3);
    v.hi.x = __uint_as_float(r4); v.hi.y = __uint_as_float(r5);
    v.hi.z = __uint_as_float(r6); v.hi.w = __uint_as_float(r7);
    return v;
}

__device__ __forceinline__ float dot8(F8 w, float4 a0, float4 a1) {
    return dot4(w.lo, a0) + dot4(w.hi, a1);
}

// PDL intrinsics (writer threads trigger after their stores; the
// memory clobber stops the compiler sinking stores below the trigger).
__device__ __forceinline__ void gdc_wait() {
    asm volatile("griddepcontrol.wait;" ::: "memory");
}
__device__ __forceinline__ void gdc_launch_dependents() {
    asm volatile("griddepcontrol.launch_dependents;" ::: "memory");
}

__device__ __forceinline__ void softmax3_cached(float& pp, float& po, float& pn) {
    float l0 = g_logits[0], l1 = g_logits[1], l2 = g_logits[2];
    float m  = fmaxf(l0, fmaxf(l1, l2));
    float e0 = __expf(l0 - m), e1 = __expf(l1 - m), e2 = __expf(l2 - m);
    float inv = 1.0f / (e0 + e1 + e2);
    pp = e0 * inv; po = e1 * inv; pn = e2 * inv;
}

// =====================================================================
// K1: fine-grained tasks to kill the ragged tail.
//   blocks [0,259):        prologue dots (3 ctrl + 256 s_in)
//   blocks [259,259+6144): gate-row tasks; g = task>>11 ∈ {r,z,n},
//                          i = task & 2047. Each: 2 dots of length H.
// =====================================================================
__global__ void __launch_bounds__(256, 6) k1_kernel(
    const float* __restrict__ hidden,
    const int*   __restrict__ inp,
    const float* __restrict__ emb,
    const float* __restrict__ W_ih,
    const float* __restrict__ W_hh,
    const float* __restrict__ Wc, const float* __restrict__ bc,
    const float* __restrict__ Ws, const float* __restrict__ bs)
{
    int b = blockIdx.x;
    int t = threadIdx.x;
    const float4* h4 = reinterpret_cast<const float4*>(hidden);
    int lane = t & 31, wid = t >> 5;

    if (b < NB_PROL) {
        __shared__ float sm1[8];
        int r = b;
        const float* rowp = (r < 3) ? (Wc + (size_t)r * H)
                                    : (Ws + (size_t)(r - 3) * H);
        F8 a = ldg_w8(rowp + t * 8);
        float4 h0 = h4[2 * t], h1 = h4[2 * t + 1];
        float s = dot8(a, h0, h1);
        #pragma unroll
        for (int o = 16; o > 0; o >>= 1) s += __shfl_down_sync(0xffffffffu, s, o);
        if (lane == 0) sm1[wid] = s;
        __syncthreads();
        if (t == 0) {
            float S = 0.f;
            #pragma unroll
            for (int j = 0; j < 8; j++) S += sm1[j];
            if (r < 3) g_logits[r] = S + bc[r];
            else       g_sin[r - 3] = tanhf(S + bs[r - 3]);
        }
        gdc_launch_dependents();
        return;
    }

    // ---------- gate-row task ----------
    int task = b - NB_PROL;
    int g = task >> 11;        // 0=r, 1=z, 2=n
    int i = task & (H - 1);

    const float* x = emb + (size_t)inp[0] * H;
    const float4* x4 = reinterpret_cast<const float4*>(x);
    float4 xv0 = x4[2 * t], xv1 = x4[2 * t + 1];
    float4 hv0 = h4[2 * t], hv1 = h4[2 * t + 1];

    F8 aw = ldg_w8(W_ih + (size_t)(g * H + i) * IH + t * 8);
    F8 bw = ldg_w8(W_hh + (size_t)(g * H + i) * H  + t * 8);
    float si = dot8(aw, xv0, xv1);   // x-part (gi, cols [0,H))
    float sh = dot8(bw, hv0, hv1);   // h-part (gh)

    __shared__ float sm[8][2];
    #pragma unroll
    for (int o = 16; o > 0; o >>= 1) {
        si += __shfl_down_sync(0xffffffffu, si, o);
        sh += __shfl_down_sync(0xffffffffu, sh, o);
    }
    if (lane == 0) { sm[wid][0] = si; sm[wid][1] = sh; }
    __syncthreads();
    if (t == 0) {
        float SI = 0.f, SH = 0.f;
        #pragma unroll
        for (int j = 0; j < 8; j++) { SI += sm[j][0]; SH += sm[j][1]; }
        if      (g == 0) g_pr[i] = SI + SH;
        else if (g == 1) g_pz[i] = SI + SH;
        else             { g_pgin[i] = SI; g_pghn[i] = SH; }
    }
    gdc_launch_dependents();   // writer (t==0) triggers after its stores
}

// =====================================================================
// K2a: blocks [0,256): GRU finish (warp per row, prefetch then wait);
//      blocks [256,306): stack update (same K1-only dependency).
// =====================================================================
__global__ void __launch_bounds__(256) k2a_kernel(
    const float* __restrict__ hidden,
    const float* __restrict__ W_ih,
    const float* __restrict__ b_ih, const float* __restrict__ b_hh,
    const float* __restrict__ stack,
    float* __restrict__ out_h, float* __restrict__ out_stack)
{
    int b = blockIdx.x;
    int t = threadIdx.x;
    int lane = t & 31, wid = t >> 5;

    if (b < NB_GRU2) {
        // ---------- GRU finish: warp `wid` owns row i ----------
        int i = 8 * b + wid;

        // prefetch: inputs independent of K1
        const float4* s0p = reinterpret_cast<const float4*>(stack);
        const float4* s1p = reinterpret_cast<const float4*>(stack + SW);
        float4 v00 = s0p[2 * lane], v01 = s0p[2 * lane + 1];
        float4 v10 = s1p[2 * lane], v11 = s1p[2 * lane + 1];

        const float* seg = W_ih + H + lane * 8;
        F8 wr8 = ldg_w8(seg + (size_t)i * IH);
        F8 wz8 = ldg_w8(seg + (size_t)(H + i) * IH);
        F8 wn8 = ldg_w8(seg + (size_t)(2 * H + i) * IH);

        float bir = 0, biz = 0, bin_ = 0, bhr = 0, bhz = 0, bhn = 0, hid = 0;
        if (lane == 0) {
            bir = b_ih[i]; biz = b_ih[H + i]; bin_ = b_ih[2 * H + i];
            bhr = b_hh[i]; bhz = b_hh[H + i]; bhn  = b_hh[2 * H + i];
            hid = hidden[i];
        }

        gdc_wait();   // K1 outputs now visible

        float pr = 0, pz = 0, pgin = 0, pghn = 0;
        if (lane == 0) {
            pr   = g_pr[i];   pz   = g_pz[i];
            pgin = g_pgin[i]; pghn = g_pghn[i];
        }
        float pp, po, pn; softmax3_cached(pp, po, pn);
        const float4* sip = reinterpret_cast<const float4*>(g_sin);
        float4 vs0 = sip[2 * lane], vs1 = sip[2 * lane + 1];

        float4 st0, st1;
        st0.x = pn*v00.x + pp*vs0.x + po*v10.x;
        st0.y = pn*v00.y + pp*vs0.y + po*v10.y;
        st0.z = pn*v00.z + pp*vs0.z + po*v10.z;
        st0.w = pn*v00.w + pp*vs0.w + po*v10.w;
        st1.x = pn*v01.x + pp*vs1.x + po*v11.x;
        st1.y = pn*v01.y + pp*vs1.y + po*v11.y;
        st1.z = pn*v01.z + pp*vs1.z + po*v11.z;
        st1.w = pn*v01.w + pp*vs1.w + po*v11.w;

        float ar = dot8(wr8, st0, st1);
        float az = dot8(wz8, st0, st1);
        float an = dot8(wn8, st0, st1);

        #pragma unroll
        for (int o = 16; o > 0; o >>= 1) {
            ar += __shfl_down_sync(0xffffffffu, ar, o);
            az += __shfl_down_sync(0xffffffffu, az, o);
            an += __shfl_down_sync(0xffffffffu, an, o);
        }
        if (lane == 0) {
            float r = 1.0f / (1.0f + expf(-(pr + ar + bir + bhr)));
            float z = 1.0f / (1.0f + expf(-(pz + az + biz + bhz)));
            float n = tanhf(pgin + an + bin_ + r * (pghn + bhn));
            float hn = (1.0f - z) * n + z * hid;
            out_h[i]  = hn;
            g_hnew[i] = hn;
        }
        gdc_launch_dependents();   // writer (lane 0) triggers after stores
        return;
    }

    // ---------- stack update: 4 depth rows per block ----------
    {
        int d = 4 * (b - NB_GRU2) + (t >> 6);
        int c = t & 63;
        // prefetch independent inputs
        float4 cur = reinterpret_cast<const float4*>(stack + (size_t)d * SW)[c];
        float4 down = make_float4(0.f, 0.f, 0.f, 0.f);
        if (d < SD - 1)
            down = reinterpret_cast<const float4*>(stack + (size_t)(d + 1) * SW)[c];
        float4 up = make_float4(0.f, 0.f, 0.f, 0.f);
        if (d > 0)
            up = reinterpret_cast<const float4*>(stack + (size_t)(d - 1) * SW)[c];

        gdc_wait();

        float pp, po, pn; softmax3_cached(pp, po, pn);
        if (d == 0)
            up = reinterpret_cast<const float4*>(g_sin)[c];
        float4 o;
        o.x = pn*cur.x + pp*up.x + po*down.x;
        o.y = pn*cur.y + pp*up.y + po*down.y;
        o.z = pn*cur.z + pp*up.z + po*down.z;
        o.w = pn*cur.w + pp*up.w + po*down.w;
        reinterpret_cast<float4*>(out_stack)[(size_t)d * (SW / 4) + c] = o;
        gdc_launch_dependents();
    }
}

// =====================================================================
// K2b: decoder only — prefetch Wd, wait on K2a, read g_hnew.
// =====================================================================
__global__ void __launch_bounds__(256) k2b_kernel(
    const float* __restrict__ Wd, const float* __restrict__ bd,
    float* __restrict__ out_o)
{
    int b = blockIdx.x;
    int t = threadIdx.x;
    F8 a = ldg_w8(Wd + (size_t)b * H + t * 8);
    float bias = (t == 0) ? bd[b] : 0.f;

    gdc_wait();   // g_hnew visible

    const float4* h4 = reinterpret_cast<const float4*>(g_hnew);
    float4 h0 = h4[2 * t], h1 = h4[2 * t + 1];
    float s = dot8(a, h0, h1);

    __shared__ float sm[8];
    int lane = t & 31, wid = t >> 5;
    #pragma unroll
    for (int o = 16; o > 0; o >>= 1) s += __shfl_down_sync(0xffffffffu, s, o);
    if (lane == 0) sm[wid] = s;
    __syncthreads();
    if (t == 0) {
        float S = 0.f;
        #pragma unroll
        for (int j = 0; j < 8; j++) S += sm[j];
        out_o[b] = S + bias;
    }
}

extern "C" void kernel_launch(void* const* d_in, const int* in_sizes, int n_in,
                              void* d_out, int out_size) {
    const int*   inp    = (const int*)  d_in[0];
    const float* hidden = (const float*)d_in[1];
    const float* stack  = (const float*)d_in[2];
    const float* emb    = (const float*)d_in[3];
    const float* Wc     = (const float*)d_in[4];
    const float* bc     = (const float*)d_in[5];
    const float* Ws     = (const float*)d_in[6];
    const float* bs     = (const float*)d_in[7];
    const float* W_ih   = (const float*)d_in[8];
    const float* b_ih   = (const float*)d_in[9];
    const float* W_hh   = (const float*)d_in[10];
    const float* b_hh   = (const float*)d_in[11];
    const float* Wd     = (const float*)d_in[12];
    const float* bd     = (const float*)d_in[13];

    float* out       = (float*)d_out;
    float* out_o     = out;            // (1,O)     : 128
    float* out_h     = out + O;        // (1,1,H)   : 2048
    float* out_stack = out + O + H;    // (1,SD,SW) : 51200

    k1_kernel<<<NB_PROL + NB_GRUT, 256>>>(hidden, inp, emb, W_ih, W_hh,
                                          Wc, bc, Ws, bs);

    cudaLaunchAttribute attr[1];
    attr[0].id = cudaLaunchAttributeProgrammaticStreamSerialization;
    attr[0].val.programmaticStreamSerializationAllowed = 1;

    {
        cudaLaunchConfig_t cfg = {};
        cfg.gridDim  = dim3(NB_GRU2 + NB_STK);
        cfg.blockDim = dim3(256);
        cfg.dynamicSmemBytes = 0;
        cfg.stream = 0;
        cfg.attrs = attr;
        cfg.numAttrs = 1;
        cudaLaunchKernelEx(&cfg, k2a_kernel, hidden, W_ih, b_ih, b_hh,
                           stack, out_h, out_stack);
    }
    {
        cudaLaunchConfig_t cfg = {};
        cfg.gridDim  = dim3(NB_DEC);
        cfg.blockDim = dim3(256);
        cfg.dynamicSmemBytes = 0;
        cfg.stream = 0;
        cfg.attrs = attr;
        cfg.numAttrs = 1;
        cudaLaunchKernelEx(&cfg, k2b_kernel, Wd, bd, out_o);
    }
}

// round 16
// speedup vs baseline: 1.1125x; 1.1125x over previous
#include <cuda_runtime.h>

#define H  2048
#define SW 256
#define SD 200
#define O  128
#define IH (H + SW)   // 2304

#define NB_PROL 259          // K1: 3 ctrl + 256 s_in dots
#define NB_GRUT (2 * H)      // K1: 2048 A-tasks (r+z) + 2048 B-tasks (n)
#define NB_GRU2 256          // K2a: 8 rows per block (warp per row)
#define NB_STK  50           // K2a: stack blocks (4 depth rows each)
#define NB_DEC  128          // K2b: decoder blocks

// ---- scratch (device globals) ----
__device__ float g_logits[3];
__device__ float g_sin[SW];
__device__ float g_pr[H];    // Wih_r[:H]·x + Whh_r·h
__device__ float g_pz[H];
__device__ float g_pgin[H];  // Wih_n[:H]·x
__device__ float g_pghn[H];  // Whh_n·h
__device__ float g_hnew[H];

struct F8 { float4 lo, hi; };

__device__ __forceinline__ float dot4(float4 a, float4 b) {
    return a.x*b.x + a.y*b.y + a.z*b.z + a.w*b.w;
}

// 256-bit read-only weight load (halves LDG count; evict-last hint kept —
// measured neutral-to-positive).
__device__ __forceinline__ F8 ldg_w8(const float* p) {
    unsigned r0, r1, r2, r3, r4, r5, r6, r7;
    asm("ld.global.nc.L2::evict_last.v8.b32 {%0,%1,%2,%3,%4,%5,%6,%7}, [%8];"
        : "=r"(r0), "=r"(r1), "=r"(r2), "=r"(r3),
          "=r"(r4), "=r"(r5), "=r"(r6), "=r"(r7)
        : "l"(p));
    F8 v;
    v.lo.x = __uint_as_float(r0); v.lo.y = __uint_as_float(r1);
    v.lo.z = __uint_as_float(r2); v.lo.w = __uint_as_float(r3);
    v.hi.x = __uint_as_float(r4); v.hi.y = __uint_as_float(r5);
    v.hi.z = __uint_as_float(r6); v.hi.w = __uint_as_float(r7);
    return v;
}

__device__ __forceinline__ float dot8(F8 w, float4 a0, float4 a1) {
    return dot4(w.lo, a0) + dot4(w.hi, a1);
}

// PDL intrinsics (writer threads trigger after their stores; the
// memory clobber stops the compiler sinking stores below the trigger).
__device__ __forceinline__ void gdc_wait() {
    asm volatile("griddepcontrol.wait;" ::: "memory");
}
__device__ __forceinline__ void gdc_launch_dependents() {
    asm volatile("griddepcontrol.launch_dependents;" ::: "memory");
}

__device__ __forceinline__ void softmax3_cached(float& pp, float& po, float& pn) {
    float l0 = g_logits[0], l1 = g_logits[1], l2 = g_logits[2];
    float m  = fmaxf(l0, fmaxf(l1, l2));
    float e0 = __expf(l0 - m), e1 = __expf(l1 - m), e2 = __expf(l2 - m);
    float inv = 1.0f / (e0 + e1 + e2);
    pp = e0 * inv; po = e1 * inv; pn = e2 * inv;
}

// =====================================================================
// K1:
//   blocks [0,259):          prologue dots (3 ctrl + 256 s_in)
//   blocks [259,259+2048):   A-tasks — r and z partials for row i
//   blocks [.. +2048):       B-tasks — n partials for row i
// =====================================================================
__global__ void __launch_bounds__(256, 6) k1_kernel(
    const float* __restrict__ hidden,
    const int*   __restrict__ inp,
    const float* __restrict__ emb,
    const float* __restrict__ W_ih,
    const float* __restrict__ W_hh,
    const float* __restrict__ Wc, const float* __restrict__ bc,
    const float* __restrict__ Ws, const float* __restrict__ bs)
{
    int b = blockIdx.x;
    int t = threadIdx.x;
    const float4* h4 = reinterpret_cast<const float4*>(hidden);
    int lane = t & 31, wid = t >> 5;

    if (b < NB_PROL) {
        __shared__ float sm1[8];
        int r = b;
        const float* rowp = (r < 3) ? (Wc + (size_t)r * H)
                                    : (Ws + (size_t)(r - 3) * H);
        F8 a = ldg_w8(rowp + t * 8);
        float4 h0 = h4[2 * t], h1 = h4[2 * t + 1];
        float s = dot8(a, h0, h1);
        #pragma unroll
        for (int o = 16; o > 0; o >>= 1) s += __shfl_down_sync(0xffffffffu, s, o);
        if (lane == 0) sm1[wid] = s;
        __syncthreads();
        if (t == 0) {
            float S = 0.f;
            #pragma unroll
            for (int j = 0; j < 8; j++) S += sm1[j];
            if (r < 3) g_logits[r] = S + bc[r];
            else       g_sin[r - 3] = tanhf(S + bs[r - 3]);
        }
        gdc_launch_dependents();
        return;
    }

    int task = b - NB_PROL;
    const float* x = emb + (size_t)inp[0] * H;
    const float4* x4 = reinterpret_cast<const float4*>(x);
    float4 xv0 = x4[2 * t], xv1 = x4[2 * t + 1];
    float4 hv0 = h4[2 * t], hv1 = h4[2 * t + 1];
    __shared__ float sm[8][2];

    if (task < H) {
        // ---------- A-task: r and z partials for row i ----------
        int i = task;
        F8 wir = ldg_w8(W_ih + (size_t)i * IH + t * 8);
        F8 whr = ldg_w8(W_hh + (size_t)i * H  + t * 8);
        F8 wiz = ldg_w8(W_ih + (size_t)(H + i) * IH + t * 8);
        F8 whz = ldg_w8(W_hh + (size_t)(H + i) * H  + t * 8);
        float pr = dot8(wir, xv0, xv1) + dot8(whr, hv0, hv1);
        float pz = dot8(wiz, xv0, xv1) + dot8(whz, hv0, hv1);

        #pragma unroll
        for (int o = 16; o > 0; o >>= 1) {
            pr += __shfl_down_sync(0xffffffffu, pr, o);
            pz += __shfl_down_sync(0xffffffffu, pz, o);
        }
        if (lane == 0) { sm[wid][0] = pr; sm[wid][1] = pz; }
        __syncthreads();
        if (t == 0) {
            float R = 0.f, Z = 0.f;
            #pragma unroll
            for (int j = 0; j < 8; j++) { R += sm[j][0]; Z += sm[j][1]; }
            g_pr[i] = R;
            g_pz[i] = Z;
        }
    } else {
        // ---------- B-task: n partials for row i ----------
        int i = task - H;
        F8 win = ldg_w8(W_ih + (size_t)(2 * H + i) * IH + t * 8);
        F8 whn = ldg_w8(W_hh + (size_t)(2 * H + i) * H  + t * 8);
        float gin = dot8(win, xv0, xv1);
        float ghn = dot8(whn, hv0, hv1);

        #pragma unroll
        for (int o = 16; o > 0; o >>= 1) {
            gin += __shfl_down_sync(0xffffffffu, gin, o);
            ghn += __shfl_down_sync(0xffffffffu, ghn, o);
        }
        if (lane == 0) { sm[wid][0] = gin; sm[wid][1] = ghn; }
        __syncthreads();
        if (t == 0) {
            float GI = 0.f, GH = 0.f;
            #pragma unroll
            for (int j = 0; j < 8; j++) { GI += sm[j][0]; GH += sm[j][1]; }
            g_pgin[i] = GI;
            g_pghn[i] = GH;
        }
    }
    gdc_launch_dependents();   // writer (t==0) triggers after its stores
}

// =====================================================================
// K2a: blocks [0,256): GRU finish (warp per row, prefetch then wait);
//      blocks [256,306): stack update (same K1-only dependency).
// =====================================================================
__global__ void __launch_bounds__(256) k2a_kernel(
    const float* __restrict__ hidden,
    const float* __restrict__ W_ih,
    const float* __restrict__ b_ih, const float* __restrict__ b_hh,
    const float* __restrict__ stack,
    float* __restrict__ out_h, float* __restrict__ out_stack)
{
    int b = blockIdx.x;
    int t = threadIdx.x;
    int lane = t & 31, wid = t >> 5;

    if (b < NB_GRU2) {
        // ---------- GRU finish: warp `wid` owns row i ----------
        int i = 8 * b + wid;

        // prefetch: inputs independent of K1
        const float4* s0p = reinterpret_cast<const float4*>(stack);
        const float4* s1p = reinterpret_cast<const float4*>(stack + SW);
        float4 v00 = s0p[2 * lane], v01 = s0p[2 * lane + 1];
        float4 v10 = s1p[2 * lane], v11 = s1p[2 * lane + 1];

        const float* seg = W_ih + H + lane * 8;
        F8 wr8 = ldg_w8(seg + (size_t)i * IH);
        F8 wz8 = ldg_w8(seg + (size_t)(H + i) * IH);
        F8 wn8 = ldg_w8(seg + (size_t)(2 * H + i) * IH);

        float bir = 0, biz = 0, bin_ = 0, bhr = 0, bhz = 0, bhn = 0, hid = 0;
        if (lane == 0) {
            bir = b_ih[i]; biz = b_ih[H + i]; bin_ = b_ih[2 * H + i];
            bhr = b_hh[i]; bhz = b_hh[H + i]; bhn  = b_hh[2 * H + i];
            hid = hidden[i];
        }

        gdc_wait();   // K1 outputs now visible

        float pr = 0, pz = 0, pgin = 0, pghn = 0;
        if (lane == 0) {
            pr   = g_pr[i];   pz   = g_pz[i];
            pgin = g_pgin[i]; pghn = g_pghn[i];
        }
        float pp, po, pn; softmax3_cached(pp, po, pn);
        const float4* sip = reinterpret_cast<const float4*>(g_sin);
        float4 vs0 = sip[2 * lane], vs1 = sip[2 * lane + 1];

        float4 st0, st1;
        st0.x = pn*v00.x + pp*vs0.x + po*v10.x;
        st0.y = pn*v00.y + pp*vs0.y + po*v10.y;
        st0.z = pn*v00.z + pp*vs0.z + po*v10.z;
        st0.w = pn*v00.w + pp*vs0.w + po*v10.w;
        st1.x = pn*v01.x + pp*vs1.x + po*v11.x;
        st1.y = pn*v01.y + pp*vs1.y + po*v11.y;
        st1.z = pn*v01.z + pp*vs1.z + po*v11.z;
        st1.w = pn*v01.w + pp*vs1.w + po*v11.w;

        float ar = dot8(wr8, st0, st1);
        float az = dot8(wz8, st0, st1);
        float an = dot8(wn8, st0, st1);

        #pragma unroll
        for (int o = 16; o > 0; o >>= 1) {
            ar += __shfl_down_sync(0xffffffffu, ar, o);
            az += __shfl_down_sync(0xffffffffu, az, o);
            an += __shfl_down_sync(0xffffffffu, an, o);
        }
        if (lane == 0) {
            float r = 1.0f / (1.0f + expf(-(pr + ar + bir + bhr)));
            float z = 1.0f / (1.0f + expf(-(pz + az + biz + bhz)));
            float n = tanhf(pgin + an + bin_ + r * (pghn + bhn));
            float hn = (1.0f - z) * n + z * hid;
            out_h[i]  = hn;
            g_hnew[i] = hn;
        }
        gdc_launch_dependents();   // writer (lane 0) triggers after stores
        return;
    }

    // ---------- stack update: 4 depth rows per block ----------
    {
        int d = 4 * (b - NB_GRU2) + (t >> 6);
        int c = t & 63;
        // prefetch independent inputs
        float4 cur = reinterpret_cast<const float4*>(stack + (size_t)d * SW)[c];
        float4 down = make_float4(0.f, 0.f, 0.f, 0.f);
        if (d < SD - 1)
            down = reinterpret_cast<const float4*>(stack + (size_t)(d + 1) * SW)[c];
        float4 up = make_float4(0.f, 0.f, 0.f, 0.f);
        if (d > 0)
            up = reinterpret_cast<const float4*>(stack + (size_t)(d - 1) * SW)[c];

        gdc_wait();

        float pp, po, pn; softmax3_cached(pp, po, pn);
        if (d == 0)
            up = reinterpret_cast<const float4*>(g_sin)[c];
        float4 o;
        o.x = pn*cur.x + pp*up.x + po*down.x;
        o.y = pn*cur.y + pp*up.y + po*down.y;
        o.z = pn*cur.z + pp*up.z + po*down.z;
        o.w = pn*cur.w + pp*up.w + po*down.w;
        reinterpret_cast<float4*>(out_stack)[(size_t)d * (SW / 4) + c] = o;
        gdc_launch_dependents();
    }
}

// =====================================================================
// K2b: decoder only — prefetch Wd, wait on K2a, read g_hnew.
// =====================================================================
__global__ void __launch_bounds__(256) k2b_kernel(
    const float* __restrict__ Wd, const float* __restrict__ bd,
    float* __restrict__ out_o)
{
    int b = blockIdx.x;
    int t = threadIdx.x;
    F8 a = ldg_w8(Wd + (size_t)b * H + t * 8);
    float bias = (t == 0) ? bd[b] : 0.f;

    gdc_wait();   // g_hnew visible

    const float4* h4 = reinterpret_cast<const float4*>(g_hnew);
    float4 h0 = h4[2 * t], h1 = h4[2 * t + 1];
    float s = dot8(a, h0, h1);

    __shared__ float sm[8];
    int lane = t & 31, wid = t >> 5;
    #pragma unroll
    for (int o = 16; o > 0; o >>= 1) s += __shfl_down_sync(0xffffffffu, s, o);
    if (lane == 0) sm[wid] = s;
    __syncthreads();
    if (t == 0) {
        float S = 0.f;
        #pragma unroll
        for (int j = 0; j < 8; j++) S += sm[j];
        out_o[b] = S + bias;
    }
}

extern "C" void kernel_launch(void* const* d_in, const int* in_sizes, int n_in,
                              void* d_out, int out_size) {
    const int*   inp    = (const int*)  d_in[0];
    const float* hidden = (const float*)d_in[1];
    const float* stack  = (const float*)d_in[2];
    const float* emb    = (const float*)d_in[3];
    const float* Wc     = (const float*)d_in[4];
    const float* bc     = (const float*)d_in[5];
    const float* Ws     = (const float*)d_in[6];
    const float* bs     = (const float*)d_in[7];
    const float* W_ih   = (const float*)d_in[8];
    const float* b_ih   = (const float*)d_in[9];
    const float* W_hh   = (const float*)d_in[10];
    const float* b_hh   = (const float*)d_in[11];
    const float* Wd     = (const float*)d_in[12];
    const float* bd     = (const float*)d_in[13];

    float* out       = (float*)d_out;
    float* out_o     = out;            // (1,O)     : 128
    float* out_h     = out + O;        // (1,1,H)   : 2048
    float* out_stack = out + O + H;    // (1,SD,SW) : 51200

    k1_kernel<<<NB_PROL + NB_GRUT, 256>>>(hidden, inp, emb, W_ih, W_hh,
                                          Wc, bc, Ws, bs);

    cudaLaunchAttribute attr[1];
    attr[0].id = cudaLaunchAttributeProgrammaticStreamSerialization;
    attr[0].val.programmaticStreamSerializationAllowed = 1;

    {
        cudaLaunchConfig_t cfg = {};
        cfg.gridDim  = dim3(NB_GRU2 + NB_STK);
        cfg.blockDim = dim3(256);
        cfg.dynamicSmemBytes = 0;
        cfg.stream = 0;
        cfg.attrs = attr;
        cfg.numAttrs = 1;
        cudaLaunchKernelEx(&cfg, k2a_kernel, hidden, W_ih, b_ih, b_hh,
                           stack, out_h, out_stack);
    }
    {
        cudaLaunchConfig_t cfg = {};
        cfg.gridDim  = dim3(NB_DEC);
        cfg.blockDim = dim3(256);
        cfg.dynamicSmemBytes = 0;
        cfg.stream = 0;
        cfg.attrs = attr;
        cfg.numAttrs = 1;
        cudaLaunchKernelEx(&cfg, k2b_kernel, Wd, bd, out_o);
    }
}